// round 2
// baseline (speedup 1.0000x reference)
#include <cuda_runtime.h>
#include <math_constants.h>

#define B_CONST 4096
#define D_CONST 256
#define N_CONST 8192
#define GRID    128
#define TPB     256

// scratch (device globals — allocation is forbidden)
__device__ float g_maxfeat[N_CONST];
__device__ int   g_idxmax[N_CONST];
__device__ int   g_barrier = 0;   // returns to 0 every launch -> replay-safe

__global__ void __launch_bounds__(TPB, 1)
fused_kernel(const float* __restrict__ a,
             const float* __restrict__ b,
             const int*   __restrict__ negc,
             float* __restrict__ out,   // [0]=loss, [1..256]=num_max
             int out_n) {
    const int tid  = threadIdx.x;
    const int bid  = blockIdx.x;
    const int warp = tid >> 5;
    const int lane = tid & 31;

    // ---- zero the output (poisoned 0xAA). Done before barrier arrive. ----
    if (bid == 0) {
        for (int i = tid; i < out_n; i += TPB) out[i] = 0.0f;
    }

    // ---- Phase 1: each warp -> 8 rows of max/argmax ----
    const int wg = bid * (TPB / 32) + warp;       // 0..1023
    #pragma unroll
    for (int r = 0; r < 8; r++) {
        const int i = wg * 8 + r;                 // row 0..8191
        const float* row = (i < B_CONST)
            ? (a + (size_t)i * D_CONST)
            : (b + (size_t)(i - B_CONST) * D_CONST);

        float best = -CUDART_INF_F;
        int bidx = 0;
        #pragma unroll
        for (int k = 0; k < D_CONST; k += 128) {
            const int c = k + lane * 4;
            float4 v = *reinterpret_cast<const float4*>(row + c);
            if (v.x > best) { best = v.x; bidx = c;     }
            if (v.y > best) { best = v.y; bidx = c + 1; }
            if (v.z > best) { best = v.z; bidx = c + 2; }
            if (v.w > best) { best = v.w; bidx = c + 3; }
        }
        // warp reduce: max value, min index on ties (matches jnp.argmax)
        #pragma unroll
        for (int off = 16; off; off >>= 1) {
            float ov = __shfl_down_sync(0xffffffffu, best, off);
            int   oi = __shfl_down_sync(0xffffffffu, bidx, off);
            if (ov > best || (ov == best && oi < bidx)) { best = ov; bidx = oi; }
        }
        if (lane == 0) {
            g_maxfeat[i] = best;
            g_idxmax[i]  = bidx;
        }
    }

    // ---- grid-wide barrier (all 128 blocks resident: 128 <= 148 SMs) ----
    __threadfence();          // publish g_maxfeat / g_idxmax / zeroed out
    __syncthreads();
    if (tid == 0) {
        const int old = atomicAdd(&g_barrier, 1);
        if (old == GRID - 1) {
            // last arriver releases everyone; counter back to 0 for next replay
            __threadfence();
            atomicExch(&g_barrier, 0);
        } else {
            while (atomicAdd(&g_barrier, 0) != 0) __nanosleep(32);
        }
    }
    __syncthreads();
    __threadfence();          // acquire side

    // ---- Phase 2: 64 rows per block -> histogram + loss ----
    float contrib = 0.0f;
    if (tid < 64) {
        const int i = bid * 64 + tid;             // row 0..8191

        // num_max histogram: 8192 atomics over 256 bins (~32 per bin)
        const int ji = g_idxmax[i];
        atomicAdd(&out[1 + ji], 1.0f);

        const int pair = (i + B_CONST) & (N_CONST - 1);
        const int e1 = min(i, pair);
        const int e2 = max(i, pair);
        int c = negc[i];
        c += (c >= e1) ? 1 : 0;
        c += (c >= e2) ? 1 : 0;

        const int j1 = g_idxmax[pair];
        const int j2 = g_idxmax[c];

        const float* row = (i < B_CONST)
            ? (a + (size_t)i * D_CONST)
            : (b + (size_t)(i - B_CONST) * D_CONST);

        const float mf  = g_maxfeat[i];
        const float pos = mf - row[j1];                 // positives[i]
        const float neg = mf - row[j2];                 // negatives[i]
        const float m   = fmaxf(1.0f - neg, 0.0f);      // clamp(MARGIN-neg,0)
        contrib = pos + m * m;
    }

    // reduce the 64 active lanes (2 warps) and accumulate loss
    #pragma unroll
    for (int off = 16; off; off >>= 1)
        contrib += __shfl_down_sync(0xffffffffu, contrib, off);
    if (tid < 64 && lane == 0)
        atomicAdd(&out[0], 0.5f * contrib);
}

extern "C" void kernel_launch(void* const* d_in, const int* in_sizes, int n_in,
                              void* d_out, int out_size) {
    const float* a    = (const float*)d_in[0];   // out_a [4096,256] f32
    const float* b    = (const float*)d_in[1];   // out_b [4096,256] f32
    const int*   negc = (const int*)  d_in[2];   // neg_choice [8192] i32
    float* out = (float*)d_out;

    fused_kernel<<<GRID, TPB>>>(a, b, negc, out, out_size);
}

// round 3
// speedup vs baseline: 1.1875x; 1.1875x over previous
#include <cuda_runtime.h>
#include <math_constants.h>

#define B_CONST 4096
#define D_CONST 256
#define N_CONST 8192
#define GRID    128
#define TPB     1024

// scratch (device globals — allocation is forbidden)
__device__ float g_maxfeat[N_CONST];
__device__ int   g_idxmax[N_CONST];
__device__ int   g_barrier = 0;   // returns to 0 every launch -> replay-safe

__device__ __forceinline__ const float* row_ptr(const float* a, const float* b, int i) {
    return (i < B_CONST) ? (a + (size_t)i * D_CONST)
                         : (b + (size_t)(i - B_CONST) * D_CONST);
}

__global__ void __launch_bounds__(TPB, 1)
fused_kernel(const float* __restrict__ a,
             const float* __restrict__ b,
             const int*   __restrict__ negc,
             float* __restrict__ out,   // [0]=loss, [1..256]=num_max
             int out_n) {
    const int tid  = threadIdx.x;
    const int bid  = blockIdx.x;
    const int warp = tid >> 5;
    const int lane = tid & 31;

    // ---- zero the output (poisoned 0xAA). Before barrier arrive. ----
    if (bid == 0) {
        for (int i = tid; i < out_n; i += TPB) out[i] = 0.0f;
    }

    // ---- Phase 1: each warp -> 2 rows; all 4 float4 loads front-batched ----
    const int wg = bid * (TPB / 32) + warp;       // 0..4095
    const int i0 = wg * 2;
    const int i1 = i0 + 1;
    const float* r0 = row_ptr(a, b, i0);
    const float* r1 = row_ptr(a, b, i1);
    const int c0 = lane * 4;
    const int c1 = 128 + lane * 4;

    float4 v00 = *reinterpret_cast<const float4*>(r0 + c0);
    float4 v01 = *reinterpret_cast<const float4*>(r0 + c1);
    float4 v10 = *reinterpret_cast<const float4*>(r1 + c0);
    float4 v11 = *reinterpret_cast<const float4*>(r1 + c1);

    // row 0: per-lane best (increasing column order -> first-occurrence ties)
    float best0 = v00.x; int bi0 = c0;
    if (v00.y > best0) { best0 = v00.y; bi0 = c0 + 1; }
    if (v00.z > best0) { best0 = v00.z; bi0 = c0 + 2; }
    if (v00.w > best0) { best0 = v00.w; bi0 = c0 + 3; }
    if (v01.x > best0) { best0 = v01.x; bi0 = c1;     }
    if (v01.y > best0) { best0 = v01.y; bi0 = c1 + 1; }
    if (v01.z > best0) { best0 = v01.z; bi0 = c1 + 2; }
    if (v01.w > best0) { best0 = v01.w; bi0 = c1 + 3; }

    float best1 = v10.x; int bi1 = c0;
    if (v10.y > best1) { best1 = v10.y; bi1 = c0 + 1; }
    if (v10.z > best1) { best1 = v10.z; bi1 = c0 + 2; }
    if (v10.w > best1) { best1 = v10.w; bi1 = c0 + 3; }
    if (v11.x > best1) { best1 = v11.x; bi1 = c1;     }
    if (v11.y > best1) { best1 = v11.y; bi1 = c1 + 1; }
    if (v11.z > best1) { best1 = v11.z; bi1 = c1 + 2; }
    if (v11.w > best1) { best1 = v11.w; bi1 = c1 + 3; }

    // warp reduce both rows: max value, min index on ties (matches jnp.argmax)
    #pragma unroll
    for (int off = 16; off; off >>= 1) {
        float ov0 = __shfl_down_sync(0xffffffffu, best0, off);
        int   oi0 = __shfl_down_sync(0xffffffffu, bi0,   off);
        float ov1 = __shfl_down_sync(0xffffffffu, best1, off);
        int   oi1 = __shfl_down_sync(0xffffffffu, bi1,   off);
        if (ov0 > best0 || (ov0 == best0 && oi0 < bi0)) { best0 = ov0; bi0 = oi0; }
        if (ov1 > best1 || (ov1 == best1 && oi1 < bi1)) { best1 = ov1; bi1 = oi1; }
    }
    if (lane == 0) {
        g_maxfeat[i0] = best0;
        g_idxmax[i0]  = bi0;
        g_maxfeat[i1] = best1;
        g_idxmax[i1]  = bi1;
    }

    // ---- grid-wide barrier (128 blocks, 1 per SM, all resident) ----
    __threadfence();
    __syncthreads();
    if (tid == 0) {
        const int old = atomicAdd(&g_barrier, 1);
        if (old == GRID - 1) {
            __threadfence();
            atomicExch(&g_barrier, 0);   // release + reset for next replay
        } else {
            while (atomicAdd(&g_barrier, 0) != 0) __nanosleep(16);
        }
    }
    __syncthreads();
    __threadfence();

    // ---- Phase 2: 64 rows per block -> histogram + loss ----
    float contrib = 0.0f;
    if (tid < 64) {
        const int i = bid * 64 + tid;

        const int ji = g_idxmax[i];
        atomicAdd(&out[1 + ji], 1.0f);   // num_max histogram

        const int pair = (i + B_CONST) & (N_CONST - 1);
        const int e1 = min(i, pair);
        const int e2 = max(i, pair);
        int c = negc[i];
        c += (c >= e1) ? 1 : 0;
        c += (c >= e2) ? 1 : 0;

        const int j1 = g_idxmax[pair];
        const int j2 = g_idxmax[c];
        const float* row = row_ptr(a, b, i);

        const float mf  = g_maxfeat[i];
        const float pos = mf - row[j1];              // positives[i]
        const float neg = mf - row[j2];              // negatives[i]
        const float m   = fmaxf(1.0f - neg, 0.0f);   // clamp(MARGIN - neg, 0)
        contrib = pos + m * m;
    }

    // reduce the 64 active lanes (2 warps) and accumulate loss
    #pragma unroll
    for (int off = 16; off; off >>= 1)
        contrib += __shfl_down_sync(0xffffffffu, contrib, off);
    if (tid < 64 && lane == 0)
        atomicAdd(&out[0], 0.5f * contrib);
}

extern "C" void kernel_launch(void* const* d_in, const int* in_sizes, int n_in,
                              void* d_out, int out_size) {
    const float* a    = (const float*)d_in[0];   // out_a [4096,256] f32
    const float* b    = (const float*)d_in[1];   // out_b [4096,256] f32
    const int*   negc = (const int*)  d_in[2];   // neg_choice [8192] i32
    float* out = (float*)d_out;

    fused_kernel<<<GRID, TPB>>>(a, b, negc, out, out_size);
}